// round 15
// baseline (speedup 1.0000x reference)
#include <cuda_runtime.h>
#include <cuda_bf16.h>
#include <cstdint>

typedef unsigned int u32;

// ---------------- scratch (device globals; no allocations allowed) ----------
__device__ u32  g_a1p[4096u*5280u];   // packed (bf16 hi, bf16 lo) post-relu conv1
__device__ u32  g_a2p[4096u*2240u];   // packed post-relu conv2
__device__ __nv_bfloat16 g_a3h[4096u*960u], g_a3l[4096u*960u]; // conv3 split planes
__device__ float g_h [4096u*512u];    // fp32 post-relu fc1
__device__ __nv_bfloat16 g_bh1[32*192],  g_bl1[32*192];   // weights [n][K] hi/lo
__device__ __nv_bfloat16 g_bh2[64*288],  g_bl2[64*288];
__device__ __nv_bfloat16 g_bh3[64*576],  g_bl3[64*576];
__device__ __nv_bfloat16 g_bh4[512*960], g_bl4[512*960];
__device__ int g_off1[192], g_off2[288], g_off3[576], g_off4[960];

// ---------------- helpers ----------------------------------------------------
__device__ __forceinline__ u32 pack_hl(float v) {
    __nv_bfloat16 h = __float2bfloat16_rn(v);
    float r = v - __bfloat162float(h);
    __nv_bfloat16 l = __float2bfloat16_rn(r);
    return ((u32)__bfloat16_as_ushort(h) << 16) | (u32)__bfloat16_as_ushort(l);
}
__device__ __forceinline__ u32 smem_u32(const void* p) {
    u32 a; asm("{ .reg .u64 t; cvta.to.shared.u64 t, %1; cvt.u32.u64 %0, t; }"
               : "=r"(a) : "l"(p));
    return a;
}

#define LDSM4(r0, r1, r2, r3, a)                                              \
    asm volatile("ldmatrix.sync.aligned.m8n8.x4.shared.b16 {%0,%1,%2,%3}, [%4];" \
        : "=r"(r0), "=r"(r1), "=r"(r2), "=r"(r3) : "r"(a))

#define MMA16816(c, a, b0, b1)                                                \
    asm volatile("mma.sync.aligned.m16n8k16.row.col.f32.bf16.bf16.f32 "       \
        "{%0,%1,%2,%3}, {%4,%5,%6,%7}, {%8,%9}, {%0,%1,%2,%3};"               \
        : "+f"((c)[0]), "+f"((c)[1]), "+f"((c)[2]), "+f"((c)[3])              \
        : "r"((a)[0]), "r"((a)[1]), "r"((a)[2]), "r"((a)[3]),                 \
          "r"(b0), "r"(b1))

#define CP_ASYNC16(dst, src)                                                  \
    asm volatile("cp.async.cg.shared.global [%0], [%1], 16;"                  \
        :: "r"(dst), "l"(src))
#define CP_COMMIT() asm volatile("cp.async.commit_group;" ::: "memory")
#define CP_WAIT0()  asm volatile("cp.async.wait_group 0;" ::: "memory")

// ---------------- prep: split weights to bf16 hi/lo + offset tables ---------
__global__ void prep_w_kernel(const float* __restrict__ w1,
                              const float* __restrict__ w2,
                              const float* __restrict__ w3,
                              const float* __restrict__ w4) {
    for (u32 i = blockIdx.x * blockDim.x + threadIdx.x; i < 491520u;
         i += gridDim.x * blockDim.x) {
        if (i < 6144) {
            float v = w1[i]; __nv_bfloat16 h = __float2bfloat16_rn(v);
            g_bh1[i] = h; g_bl1[i] = __float2bfloat16_rn(v - __bfloat162float(h));
        }
        if (i < 18432) {
            float v = w2[i]; __nv_bfloat16 h = __float2bfloat16_rn(v);
            g_bh2[i] = h; g_bl2[i] = __float2bfloat16_rn(v - __bfloat162float(h));
        }
        if (i < 36864) {
            float v = w3[i]; __nv_bfloat16 h = __float2bfloat16_rn(v);
            g_bh3[i] = h; g_bl3[i] = __float2bfloat16_rn(v - __bfloat162float(h));
        }
        {
            float v = w4[i]; __nv_bfloat16 h = __float2bfloat16_rn(v);
            g_bh4[i] = h; g_bl4[i] = __float2bfloat16_rn(v - __bfloat162float(h));
        }
        if (i < 192) { int ci = i >> 6, r = i & 63; g_off1[i] = ci * 3072 + (r >> 3) * 64 + (r & 7); }
        if (i < 288) { int ci = i / 9, r = i % 9; g_off2[i] = ci * 165 + (r / 3) * 15 + r % 3; }
        if (i < 576) { int ci = i / 9, r = i % 9; g_off3[i] = ci * 35 + (r / 3) * 7 + r % 3; }
        if (i < 960) g_off4[i] = i;
    }
}

__global__ void aveinit_kernel(const float* __restrict__ b1,
                               const float* __restrict__ b2,
                               const float* __restrict__ b3,
                               float* __restrict__ out) {
    int t = threadIdx.x;
    if (t < 165) {
        float s = 0.f; for (int c = 0; c < 32; c++) s += b1[c];
        out[8192 + t] = 4096.f * s / 32.f;
    } else if (t < 200) {
        float s = 0.f; for (int c = 0; c < 64; c++) s += b2[c];
        out[8192 + 165 + (t - 165)] = 4096.f * s / 64.f;
    } else if (t < 215) {
        float s = 0.f; for (int c = 0; c < 64; c++) s += b3[c];
        out[8192 + 200 + (t - 200)] = 4096.f * s / 64.f;
    }
}

// ---------------- unified HMMA gather-GEMM (im2col conv / fc) ---------------
// bf16-split: D = AhBh + AhBl + AlBh in fp32 via mma.sync m16n8k16.
// Gather+store FUSED at top of each chunk (gather regs dead during mma ->
// low reg pressure -> MINB=3 CTAs/SM for conv2/3/fc1). B (and fc1-A) via
// cp.async, completed under the mma phase. Tiles pitch 80B, double-buffered.
template<int LAYER, int NT, int WM, int MROWS, int MINB>
__global__ __launch_bounds__(256, MINB) void conv_hmma(
    const float* __restrict__ src_ext,   // LAYER==1: x (fp32)
    const float* __restrict__ bias, float* __restrict__ ave) {

    constexpr int K       = LAYER == 1 ? 192  : LAYER == 2 ? 288 : LAYER == 3 ? 576 : 960;
    constexpr int npos    = LAYER == 1 ? 165  : LAYER == 2 ? 35  : LAYER == 3 ? 15  : 1;
    constexpr int imgstr  = LAYER == 1 ? 9216 : LAYER == 2 ? 5280: LAYER == 3 ? 2240: 960;
    constexpr int PW      = LAYER == 1 ? 15   : LAYER == 2 ? 7   : LAYER == 3 ? 5   : 1;
    constexpr int rowstep = LAYER == 1 ? 256  : LAYER == 2 ? 30  : LAYER == 3 ? 7   : 0;
    constexpr int colstep = LAYER == 1 ? 4    : LAYER == 2 ? 2   : LAYER == 3 ? 1   : 0;
    constexpr int ocs     = LAYER == 1 ? 165  : LAYER == 2 ? 35  : LAYER == 3 ? 15  : 1;
    constexpr int cstride = LAYER == 1 ? 5280 : LAYER == 2 ? 2240: LAYER == 3 ? 960 : 512;
    constexpr float invC  = LAYER == 1 ? (1.f / 32.f) : (1.f / 64.f);
    constexpr bool AVE    = LAYER != 4;
    constexpr int NCH = K / 32;
    constexpr int MT  = WM / 16;
    constexpr int NWN = NT / 32;
    constexpr int NRB = MROWS / 64;          // A gather row-iters per thread
    constexpr int PITCH = 80;
    constexpr int PL  = MROWS * PITCH;       // one A plane
    constexpr int A_HI = 0, A_LO = PL, B_HI = 2 * PL;
    constexpr int BUF = 2 * PL + NT * 160;   // per-buffer bytes

    const u32* srcp; const char *bhp, *blp; const int* offtab;
    if constexpr (LAYER == 1) { srcp = nullptr; offtab = g_off1; bhp = (const char*)g_bh1; blp = (const char*)g_bl1; }
    if constexpr (LAYER == 2) { srcp = g_a1p; offtab = g_off2; bhp = (const char*)g_bh2; blp = (const char*)g_bl2; }
    if constexpr (LAYER == 3) { srcp = g_a2p; offtab = g_off3; bhp = (const char*)g_bh3; blp = (const char*)g_bl3; }
    if constexpr (LAYER == 4) { srcp = nullptr; offtab = g_off4; bhp = (const char*)g_bh4; blp = (const char*)g_bl4; }

    extern __shared__ __align__(128) char smem[];
    const u32 sb = smem_u32(smem);
    int* soff  = (int*)(smem + 2 * BUF);  // [K]
    int* sbase = soff + K;                // [MROWS]
    int* sdst  = sbase + MROWS;           // [MROWS]
    int* spos  = sdst + MROWS;            // [MROWS]
    float* sred = (float*)(spos + MROWS); // [MROWS]

    const int tid = threadIdx.x;
    const int wid = tid >> 5, l = tid & 31;
    const int wm = wid / NWN, wn = wid % NWN;
    const int m0 = blockIdx.x * MROWS;
    const int n0g = (LAYER == 4) ? blockIdx.y * 64 : 0;

    for (int i = tid; i < K; i += 256) soff[i] = offtab[i];
    for (int i = tid; i < MROWS; i += 256) {
        int m = m0 + i;
        int img = m / npos, pos = m - img * npos;
        int py = pos / PW, px = pos - py * PW;
        sbase[i] = img * imgstr + py * rowstep + px * colstep;
        sdst[i]  = img * cstride + pos;
        spos[i]  = pos;
        sred[i]  = 0.f;
    }
    __syncthreads();

    // A gather geometry: m = wid*(MROWS/8) + (l>>2) + 8i (i<NRB), kw = (l&3)+4j
    const int gm = wid * (MROWS / 8) + (l >> 2);
    const int gk = l & 3;
    int rb[NRB];
#pragma unroll
    for (int i = 0; i < NRB; i++) rb[i] = sbase[gm + 8 * i];
    // B: thread -> (row n, 16B block)
    const int bn = tid >> 2, bblk = tid & 3;
    const bool bact = tid < NT * 4;

    // ldmatrix lane addresses (buffer 0; add bufoff + ks8*32 at use)
    u32 aAddr[MT], bAddr[2];
#pragma unroll
    for (int t = 0; t < MT; t++)
        aAddr[t] = sb + A_HI + (u32)(wm * WM + t * 16 + (l & 15)) * PITCH
                 + (u32)((l >> 4) & 1) * 16;
#pragma unroll
    for (int g = 0; g < 2; g++)
        bAddr[g] = sb + B_HI + (u32)(wn * 32 + g * 16 + (l & 7) + ((l >> 4) & 1) * 8) * PITCH
                 + (u32)((l >> 3) & 1) * 16;

    float c[MT][4][4];
#pragma unroll
    for (int t = 0; t < MT; t++)
#pragma unroll
        for (int n = 0; n < 4; n++)
#pragma unroll
            for (int e = 0; e < 4; e++) c[t][n][e] = 0.f;

    // ---- stage one chunk: A gather->regs->smem fused (regs die here);
    //      B tiles (and fc1 A) via cp.async ----
    auto stage = [&](int cc, int buf) {
        const int kc = cc * 32;
        if constexpr (LAYER != 4) {
            char* base = smem + buf * BUF;
#pragma unroll
            for (int i = 0; i < NRB; i++)
#pragma unroll
                for (int j = 0; j < 4; j++) {
                    int kw = gk + 4 * j;
                    u32 p0, p1;
                    if constexpr (LAYER == 1) {
                        float2 v = *(const float2*)(src_ext + rb[i] + soff[kc + 2 * kw]);
                        p0 = pack_hl(v.x); p1 = pack_hl(v.y);
                    } else {
                        int o0 = soff[kc + 2 * kw], o1 = soff[kc + 2 * kw + 1];
                        p0 = srcp[rb[i] + o0]; p1 = srcp[rb[i] + o1];
                    }
                    u32 off = (u32)(gm + 8 * i) * PITCH + (u32)kw * 4;
                    *(u32*)(base + A_HI + off) = __byte_perm(p0, p1, 0x7632);
                    *(u32*)(base + A_LO + off) = __byte_perm(p0, p1, 0x5410);
                }
        } else {
            const __nv_bfloat16* plane = (tid & 1) ? g_a3l : g_a3h;
            int m = tid >> 1;
            u32 dst = sb + buf * BUF + ((tid & 1) ? A_LO : A_HI) + (u32)m * PITCH;
            const char* src = (const char*)(plane + sbase[m] + kc);
#pragma unroll
            for (int s = 0; s < 4; s++) CP_ASYNC16(dst + s * 16, src + s * 16);
        }
        if (bact) {
            size_t boff = (size_t)(n0g + bn) * (2 * K) + cc * 64 + bblk * 16;
            u32 dst = sb + buf * BUF + B_HI + (u32)bn * PITCH + (u32)bblk * 16;
            CP_ASYNC16(dst, bhp + boff);
            CP_ASYNC16(dst + NT * PITCH, blp + boff);
        }
        CP_COMMIT();
    };

    // prologue: stage chunk 0
    stage(0, 0);
    CP_WAIT0();
    __syncthreads();

    for (int cc = 0; cc < NCH; cc++) {
        // stage chunk cc+1 into buffer (cc+1)&1 (freed by previous barrier)
        if (cc + 1 < NCH) stage(cc + 1, (cc + 1) & 1);

        const u32 bufoff = (u32)(cc & 1) * BUF;
#pragma unroll
        for (int ks8 = 0; ks8 < 2; ks8++) {
            u32 ah[MT][4], al[MT][4], bhf[2][4], blf[2][4];
#pragma unroll
            for (int t = 0; t < MT; t++) {
                LDSM4(ah[t][0], ah[t][1], ah[t][2], ah[t][3], aAddr[t] + bufoff + ks8 * 32);
                LDSM4(al[t][0], al[t][1], al[t][2], al[t][3], aAddr[t] + bufoff + ks8 * 32 + PL);
            }
#pragma unroll
            for (int g = 0; g < 2; g++) {
                LDSM4(bhf[g][0], bhf[g][1], bhf[g][2], bhf[g][3], bAddr[g] + bufoff + ks8 * 32);
                LDSM4(blf[g][0], blf[g][1], blf[g][2], blf[g][3], bAddr[g] + bufoff + ks8 * 32 + NT * PITCH);
            }
#pragma unroll
            for (int t = 0; t < MT; t++)
#pragma unroll
                for (int g = 0; g < 2; g++)
#pragma unroll
                    for (int h = 0; h < 2; h++) {
                        int nt = g * 2 + h;
                        MMA16816(c[t][nt], ah[t], bhf[g][2 * h], bhf[g][2 * h + 1]);
                        MMA16816(c[t][nt], ah[t], blf[g][2 * h], blf[g][2 * h + 1]);
                        MMA16816(c[t][nt], al[t], bhf[g][2 * h], bhf[g][2 * h + 1]);
                    }
        }
        if (cc + 1 < NCH) CP_WAIT0();
        __syncthreads();
    }

    // ---- epilogue: bias + relu (+ pack / split), ave row sums ----
#pragma unroll
    for (int t = 0; t < MT; t++) {
        int r0 = wm * WM + t * 16 + (l >> 2);
        int r1 = r0 + 8;
        int db0 = sdst[r0], db1 = sdst[r1];
        float s0 = 0.f, s1 = 0.f;
#pragma unroll
        for (int nt = 0; nt < 4; nt++)
#pragma unroll
            for (int e = 0; e < 2; e++) {
                int n = wn * 32 + nt * 8 + ((l & 3) << 1) + e;
                float v0 = c[t][nt][e], v1 = c[t][nt][2 + e];
                s0 += v0; s1 += v1;
                float bb = __ldg(&bias[n0g + n]);
                float o0 = fmaxf(v0 + bb, 0.f), o1 = fmaxf(v1 + bb, 0.f);
                if constexpr (LAYER == 1) { g_a1p[db0 + n * ocs] = pack_hl(o0); g_a1p[db1 + n * ocs] = pack_hl(o1); }
                if constexpr (LAYER == 2) { g_a2p[db0 + n * ocs] = pack_hl(o0); g_a2p[db1 + n * ocs] = pack_hl(o1); }
                if constexpr (LAYER == 3) {
                    __nv_bfloat16 h0 = __float2bfloat16_rn(o0);
                    __nv_bfloat16 h1 = __float2bfloat16_rn(o1);
                    g_a3h[db0 + n * ocs] = h0;
                    g_a3l[db0 + n * ocs] = __float2bfloat16_rn(o0 - __bfloat162float(h0));
                    g_a3h[db1 + n * ocs] = h1;
                    g_a3l[db1 + n * ocs] = __float2bfloat16_rn(o1 - __bfloat162float(h1));
                }
                if constexpr (LAYER == 4) { g_h[db0 + n0g + n] = o0; g_h[db1 + n0g + n] = o1; }
            }
        if constexpr (AVE) {
            atomicAdd(&sred[r0], s0);
            atomicAdd(&sred[r1], s1);
        }
    }
    if constexpr (AVE) {
        __syncthreads();
        for (int i = tid; i < MROWS; i += 256)
            atomicAdd(&ave[spos[i]], sred[i] * invC);
    }
}

// ---------------- fc2: [4096,512] x [2,512]^T + b ---------------------------
__global__ __launch_bounds__(256) void fc2_kernel(
    const float* __restrict__ w5, const float* __restrict__ b5,
    float* __restrict__ out) {
    int b = blockIdx.x * blockDim.x + threadIdx.x;
    if (b >= 4096) return;
    const float4* h4 = (const float4*)(g_h + (size_t)b * 512);
    const float4* wa = (const float4*)w5;
    const float4* wb = (const float4*)(w5 + 512);
    float s0 = 0.0f, s1 = 0.0f;
#pragma unroll 4
    for (int i = 0; i < 128; i++) {
        float4 h = h4[i];
        float4 a = __ldg(&wa[i]);
        float4 c = __ldg(&wb[i]);
        s0 += h.x * a.x + h.y * a.y + h.z * a.z + h.w * a.w;
        s1 += h.x * c.x + h.y * c.y + h.z * c.z + h.w * c.w;
    }
    out[b * 2 + 0] = s0 + __ldg(&b5[0]);
    out[b * 2 + 1] = s1 + __ldg(&b5[1]);
}

// ---------------- launch ----------------------------------------------------
extern "C" void kernel_launch(void* const* d_in, const int* in_sizes, int n_in,
                              void* d_out, int out_size) {
    const float* x  = (const float*)d_in[0];
    const float* w1 = (const float*)d_in[1];
    const float* b1 = (const float*)d_in[2];
    const float* w2 = (const float*)d_in[3];
    const float* b2 = (const float*)d_in[4];
    const float* w3 = (const float*)d_in[5];
    const float* b3 = (const float*)d_in[6];
    const float* w4 = (const float*)d_in[7];
    const float* b4 = (const float*)d_in[8];
    const float* w5 = (const float*)d_in[9];
    const float* b5 = (const float*)d_in[10];

    float* out  = (float*)d_out;
    float* ave1 = out + 8192;        // 165
    float* ave2 = out + 8192 + 165;  // 35
    float* ave3 = out + 8192 + 200;  // 15

    prep_w_kernel<<<480, 256>>>(w1, w2, w3, w4);
    aveinit_kernel<<<1, 256>>>(b1, b2, b3, out);

    // dynamic smem: 2*BUF + 4*K + 16*MROWS ; BUF = 160*MROWS + 160*NT
    const int sm1 = 2 * (160 * 256 + 160 * 32) + 4 * 192 + 16 * 256;  // 97024
    const int sm2 = 2 * (160 * 128 + 160 * 64) + 4 * 288 + 16 * 128;  // 64640
    const int sm3 = 2 * (160 * 128 + 160 * 64) + 4 * 576 + 16 * 128;  // 65792
    const int sm4 = 2 * (160 * 128 + 160 * 64) + 4 * 960 + 16 * 128;  // 67328
    cudaFuncSetAttribute(conv_hmma<1, 32, 32, 256, 2>, cudaFuncAttributeMaxDynamicSharedMemorySize, sm1);
    cudaFuncSetAttribute(conv_hmma<2, 64, 32, 128, 3>, cudaFuncAttributeMaxDynamicSharedMemorySize, sm2);
    cudaFuncSetAttribute(conv_hmma<3, 64, 32, 128, 3>, cudaFuncAttributeMaxDynamicSharedMemorySize, sm3);
    cudaFuncSetAttribute(conv_hmma<4, 64, 32, 128, 3>, cudaFuncAttributeMaxDynamicSharedMemorySize, sm4);

    conv_hmma<1, 32, 32, 256, 2><<<2640, 256, sm1>>>(x, b1, ave1);          // M=675840
    conv_hmma<2, 64, 32, 128, 3><<<1120, 256, sm2>>>(nullptr, b2, ave2);    // M=143360
    conv_hmma<3, 64, 32, 128, 3><<<480, 256, sm3>>>(nullptr, b3, ave3);     // M=61440
    {
        dim3 grid(32, 8);                                                   // M=4096, N=512
        conv_hmma<4, 64, 32, 128, 3><<<grid, 256, sm4>>>(nullptr, b4, nullptr);
    }
    fc2_kernel<<<16, 256>>>(w5, b5, out);
}

// round 16
// speedup vs baseline: 1.7618x; 1.7618x over previous
#include <cuda_runtime.h>
#include <cuda_bf16.h>
#include <cstdint>

typedef unsigned int u32;

// ---------------- scratch (device globals; no allocations allowed) ----------
__device__ u32  g_a1p[4096u*5280u];   // packed (bf16 hi, bf16 lo) post-relu conv1
__device__ u32  g_a2p[4096u*2240u];   // packed post-relu conv2
__device__ __nv_bfloat16 g_a3h[4096u*960u], g_a3l[4096u*960u]; // conv3 split planes
__device__ float g_h [4096u*512u];    // fp32 post-relu fc1
__device__ __nv_bfloat16 g_bh1[32*192],  g_bl1[32*192];   // weights [n][K] hi/lo
__device__ __nv_bfloat16 g_bh2[64*288],  g_bl2[64*288];
__device__ __nv_bfloat16 g_bh3[64*576],  g_bl3[64*576];
__device__ __nv_bfloat16 g_bh4[512*960], g_bl4[512*960];
__device__ int g_off1[192], g_off2[288], g_off3[576], g_off4[960];

// ---------------- helpers ----------------------------------------------------
__device__ __forceinline__ u32 pack_hl(float v) {
    __nv_bfloat16 h = __float2bfloat16_rn(v);
    float r = v - __bfloat162float(h);
    __nv_bfloat16 l = __float2bfloat16_rn(r);
    return ((u32)__bfloat16_as_ushort(h) << 16) | (u32)__bfloat16_as_ushort(l);
}
__device__ __forceinline__ u32 smem_u32(const void* p) {
    u32 a; asm("{ .reg .u64 t; cvta.to.shared.u64 t, %1; cvt.u32.u64 %0, t; }"
               : "=r"(a) : "l"(p));
    return a;
}

#define LDSM4(r0, r1, r2, r3, a)                                              \
    asm volatile("ldmatrix.sync.aligned.m8n8.x4.shared.b16 {%0,%1,%2,%3}, [%4];" \
        : "=r"(r0), "=r"(r1), "=r"(r2), "=r"(r3) : "r"(a))

#define MMA16816(c, a, b0, b1)                                                \
    asm volatile("mma.sync.aligned.m16n8k16.row.col.f32.bf16.bf16.f32 "       \
        "{%0,%1,%2,%3}, {%4,%5,%6,%7}, {%8,%9}, {%0,%1,%2,%3};"               \
        : "+f"((c)[0]), "+f"((c)[1]), "+f"((c)[2]), "+f"((c)[3])              \
        : "r"((a)[0]), "r"((a)[1]), "r"((a)[2]), "r"((a)[3]),                 \
          "r"(b0), "r"(b1))

#define CP_ASYNC16(dst, src)                                                  \
    asm volatile("cp.async.cg.shared.global [%0], [%1], 16;"                  \
        :: "r"(dst), "l"(src))
#define CP_COMMIT() asm volatile("cp.async.commit_group;" ::: "memory")
#define CP_WAIT0()  asm volatile("cp.async.wait_group 0;" ::: "memory")

// ---------------- prep: split weights to bf16 hi/lo + offset tables ---------
__global__ void prep_w_kernel(const float* __restrict__ w1,
                              const float* __restrict__ w2,
                              const float* __restrict__ w3,
                              const float* __restrict__ w4) {
    for (u32 i = blockIdx.x * blockDim.x + threadIdx.x; i < 491520u;
         i += gridDim.x * blockDim.x) {
        if (i < 6144) {
            float v = w1[i]; __nv_bfloat16 h = __float2bfloat16_rn(v);
            g_bh1[i] = h; g_bl1[i] = __float2bfloat16_rn(v - __bfloat162float(h));
        }
        if (i < 18432) {
            float v = w2[i]; __nv_bfloat16 h = __float2bfloat16_rn(v);
            g_bh2[i] = h; g_bl2[i] = __float2bfloat16_rn(v - __bfloat162float(h));
        }
        if (i < 36864) {
            float v = w3[i]; __nv_bfloat16 h = __float2bfloat16_rn(v);
            g_bh3[i] = h; g_bl3[i] = __float2bfloat16_rn(v - __bfloat162float(h));
        }
        {
            float v = w4[i]; __nv_bfloat16 h = __float2bfloat16_rn(v);
            g_bh4[i] = h; g_bl4[i] = __float2bfloat16_rn(v - __bfloat162float(h));
        }
        if (i < 192) { int ci = i >> 6, r = i & 63; g_off1[i] = ci * 3072 + (r >> 3) * 64 + (r & 7); }
        if (i < 288) { int ci = i / 9, r = i % 9; g_off2[i] = ci * 165 + (r / 3) * 15 + r % 3; }
        if (i < 576) { int ci = i / 9, r = i % 9; g_off3[i] = ci * 35 + (r / 3) * 7 + r % 3; }
        if (i < 960) g_off4[i] = i;
    }
}

__global__ void aveinit_kernel(const float* __restrict__ b1,
                               const float* __restrict__ b2,
                               const float* __restrict__ b3,
                               float* __restrict__ out) {
    int t = threadIdx.x;
    if (t < 165) {
        float s = 0.f; for (int c = 0; c < 32; c++) s += b1[c];
        out[8192 + t] = 4096.f * s / 32.f;
    } else if (t < 200) {
        float s = 0.f; for (int c = 0; c < 64; c++) s += b2[c];
        out[8192 + 165 + (t - 165)] = 4096.f * s / 64.f;
    } else if (t < 215) {
        float s = 0.f; for (int c = 0; c < 64; c++) s += b3[c];
        out[8192 + 200 + (t - 200)] = 4096.f * s / 64.f;
    }
}

// ---------------- unified HMMA gather-GEMM (im2col conv / fc) ---------------
// bf16-split: D = AhBh + AhBl + AlBh in fp32 via mma.sync m16n8k16.
// R12 schedule (measured best): gather chunk cc+1 into regs at top of iter cc
// (LDG latency hidden under mma), store to smem after mma, one barrier/chunk.
// B (and fc1-A) tiles via cp.async. Tiles pitch 80B, double-buffered.
template<int LAYER, int NT, int WM, int MROWS>
__global__ __launch_bounds__(256, 2) void conv_hmma(
    const float* __restrict__ src_ext,   // LAYER==1: x (fp32)
    const float* __restrict__ bias, float* __restrict__ ave) {

    constexpr int K       = LAYER == 1 ? 192  : LAYER == 2 ? 288 : LAYER == 3 ? 576 : 960;
    constexpr int npos    = LAYER == 1 ? 165  : LAYER == 2 ? 35  : LAYER == 3 ? 15  : 1;
    constexpr int imgstr  = LAYER == 1 ? 9216 : LAYER == 2 ? 5280: LAYER == 3 ? 2240: 960;
    constexpr int PW      = LAYER == 1 ? 15   : LAYER == 2 ? 7   : LAYER == 3 ? 5   : 1;
    constexpr int rowstep = LAYER == 1 ? 256  : LAYER == 2 ? 30  : LAYER == 3 ? 7   : 0;
    constexpr int colstep = LAYER == 1 ? 4    : LAYER == 2 ? 2   : LAYER == 3 ? 1   : 0;
    constexpr int ocs     = LAYER == 1 ? 165  : LAYER == 2 ? 35  : LAYER == 3 ? 15  : 1;
    constexpr int cstride = LAYER == 1 ? 5280 : LAYER == 2 ? 2240: LAYER == 3 ? 960 : 512;
    constexpr float invC  = LAYER == 1 ? (1.f / 32.f) : (1.f / 64.f);
    constexpr bool AVE    = LAYER != 4;
    constexpr int NCH = K / 32;
    constexpr int MT  = WM / 16;
    constexpr int NWN = NT / 32;
    constexpr int NRB = MROWS / 64;          // A gather row-iters per thread
    constexpr int PITCH = 80;
    constexpr int PL  = MROWS * PITCH;       // one A plane
    constexpr int A_HI = 0, A_LO = PL, B_HI = 2 * PL;
    constexpr int BUF = 2 * PL + NT * 160;   // per-buffer bytes

    const u32* srcp; const char *bhp, *blp; const int* offtab;
    if constexpr (LAYER == 1) { srcp = nullptr; offtab = g_off1; bhp = (const char*)g_bh1; blp = (const char*)g_bl1; }
    if constexpr (LAYER == 2) { srcp = g_a1p; offtab = g_off2; bhp = (const char*)g_bh2; blp = (const char*)g_bl2; }
    if constexpr (LAYER == 3) { srcp = g_a2p; offtab = g_off3; bhp = (const char*)g_bh3; blp = (const char*)g_bl3; }
    if constexpr (LAYER == 4) { srcp = nullptr; offtab = g_off4; bhp = (const char*)g_bh4; blp = (const char*)g_bl4; }

    extern __shared__ __align__(128) char smem[];
    const u32 sb = smem_u32(smem);
    int* soff  = (int*)(smem + 2 * BUF);  // [K]
    int* sbase = soff + K;                // [MROWS]
    int* sdst  = sbase + MROWS;           // [MROWS]
    int* spos  = sdst + MROWS;            // [MROWS]
    float* sred = (float*)(spos + MROWS); // [MROWS]

    const int tid = threadIdx.x;
    const int wid = tid >> 5, l = tid & 31;
    const int wm = wid / NWN, wn = wid % NWN;
    const int m0 = blockIdx.x * MROWS;
    const int n0g = (LAYER == 4) ? blockIdx.y * 64 : 0;

    for (int i = tid; i < K; i += 256) soff[i] = offtab[i];
    for (int i = tid; i < MROWS; i += 256) {
        int m = m0 + i;
        int img = m / npos, pos = m - img * npos;
        int py = pos / PW, px = pos - py * PW;
        sbase[i] = img * imgstr + py * rowstep + px * colstep;
        sdst[i]  = img * cstride + pos;
        spos[i]  = pos;
        sred[i]  = 0.f;
    }
    __syncthreads();

    // A gather geometry: m = wid*(MROWS/8) + (l>>2) + 8i (i<NRB), kw = (l&3)+4j
    const int gm = wid * (MROWS / 8) + (l >> 2);
    const int gk = l & 3;
    int rb[NRB];
#pragma unroll
    for (int i = 0; i < NRB; i++) rb[i] = sbase[gm + 8 * i];
    // B: thread -> (row n, 16B block)
    const int bn = tid >> 2, bblk = tid & 3;
    const bool bact = tid < NT * 4;

    // ldmatrix lane addresses (buffer 0; add bufoff + ks8*32 at use)
    u32 aAddr[MT], bAddr[2];
#pragma unroll
    for (int t = 0; t < MT; t++)
        aAddr[t] = sb + A_HI + (u32)(wm * WM + t * 16 + (l & 15)) * PITCH
                 + (u32)((l >> 4) & 1) * 16;
#pragma unroll
    for (int g = 0; g < 2; g++)
        bAddr[g] = sb + B_HI + (u32)(wn * 32 + g * 16 + (l & 7) + ((l >> 4) & 1) * 8) * PITCH
                 + (u32)((l >> 3) & 1) * 16;

    float c[MT][4][4];
#pragma unroll
    for (int t = 0; t < MT; t++)
#pragma unroll
        for (int n = 0; n < 4; n++)
#pragma unroll
            for (int e = 0; e < 4; e++) c[t][n][e] = 0.f;

    u32 ha[4 * NRB], la[4 * NRB];

    // ---- gather one chunk: A conv -> regs; A fc + all B -> cp.async ----
    auto gather = [&](int cc, int buf) {
        const int kc = cc * 32;
        if constexpr (LAYER == 4) {
            const __nv_bfloat16* plane = (tid & 1) ? g_a3l : g_a3h;
            int m = tid >> 1;
            u32 dst = sb + buf * BUF + ((tid & 1) ? A_LO : A_HI) + (u32)m * PITCH;
            const char* src = (const char*)(plane + sbase[m] + kc);
#pragma unroll
            for (int s = 0; s < 4; s++) CP_ASYNC16(dst + s * 16, src + s * 16);
        } else {
#pragma unroll
            for (int i = 0; i < NRB; i++)
#pragma unroll
                for (int j = 0; j < 4; j++) {
                    int kw = gk + 4 * j;
                    int e = i * 4 + j;
                    u32 p0, p1;
                    if constexpr (LAYER == 1) {
                        float2 v = *(const float2*)(src_ext + rb[i] + soff[kc + 2 * kw]);
                        p0 = pack_hl(v.x); p1 = pack_hl(v.y);
                    } else {
                        int o0 = soff[kc + 2 * kw], o1 = soff[kc + 2 * kw + 1];
                        p0 = srcp[rb[i] + o0]; p1 = srcp[rb[i] + o1];
                    }
                    ha[e] = __byte_perm(p0, p1, 0x7632);
                    la[e] = __byte_perm(p0, p1, 0x5410);
                }
        }
        if (bact) {
            size_t boff = (size_t)(n0g + bn) * (2 * K) + cc * 64 + bblk * 16;
            u32 dst = sb + buf * BUF + B_HI + (u32)bn * PITCH + (u32)bblk * 16;
            CP_ASYNC16(dst, bhp + boff);
            CP_ASYNC16(dst + NT * PITCH, blp + boff);
        }
        CP_COMMIT();
    };
    // ---- A regs -> smem (conv layers only) ----
    auto store = [&](int buf) {
        if constexpr (LAYER != 4) {
            char* base = smem + buf * BUF;
#pragma unroll
            for (int i = 0; i < NRB; i++)
#pragma unroll
                for (int j = 0; j < 4; j++) {
                    u32 off = (u32)(gm + 8 * i) * PITCH + (u32)(gk + 4 * j) * 4;
                    *(u32*)(base + A_HI + off) = ha[i * 4 + j];
                    *(u32*)(base + A_LO + off) = la[i * 4 + j];
                }
        }
    };

    gather(0, 0);
    store(0);
    CP_WAIT0();
    __syncthreads();

    for (int cc = 0; cc < NCH; cc++) {
        if (cc + 1 < NCH) gather(cc + 1, (cc + 1) & 1);   // latency hides under mma
        const u32 bufoff = (u32)(cc & 1) * BUF;
#pragma unroll
        for (int ks8 = 0; ks8 < 2; ks8++) {
            u32 ah[MT][4], al[MT][4], bhf[2][4], blf[2][4];
#pragma unroll
            for (int t = 0; t < MT; t++) {
                LDSM4(ah[t][0], ah[t][1], ah[t][2], ah[t][3], aAddr[t] + bufoff + ks8 * 32);
                LDSM4(al[t][0], al[t][1], al[t][2], al[t][3], aAddr[t] + bufoff + ks8 * 32 + PL);
            }
#pragma unroll
            for (int g = 0; g < 2; g++) {
                LDSM4(bhf[g][0], bhf[g][1], bhf[g][2], bhf[g][3], bAddr[g] + bufoff + ks8 * 32);
                LDSM4(blf[g][0], blf[g][1], blf[g][2], blf[g][3], bAddr[g] + bufoff + ks8 * 32 + NT * PITCH);
            }
#pragma unroll
            for (int t = 0; t < MT; t++)
#pragma unroll
                for (int g = 0; g < 2; g++)
#pragma unroll
                    for (int h = 0; h < 2; h++) {
                        int nt = g * 2 + h;
                        MMA16816(c[t][nt], ah[t], bhf[g][2 * h], bhf[g][2 * h + 1]);
                        MMA16816(c[t][nt], ah[t], blf[g][2 * h], blf[g][2 * h + 1]);
                        MMA16816(c[t][nt], al[t], bhf[g][2 * h], bhf[g][2 * h + 1]);
                    }
        }
        if (cc + 1 < NCH) { store((cc + 1) & 1); CP_WAIT0(); }
        __syncthreads();
    }

    // ---- epilogue: bias + relu (+ pack / split), ave row sums ----
#pragma unroll
    for (int t = 0; t < MT; t++) {
        int r0 = wm * WM + t * 16 + (l >> 2);
        int r1 = r0 + 8;
        int db0 = sdst[r0], db1 = sdst[r1];
        float s0 = 0.f, s1 = 0.f;
#pragma unroll
        for (int nt = 0; nt < 4; nt++)
#pragma unroll
            for (int e = 0; e < 2; e++) {
                int n = wn * 32 + nt * 8 + ((l & 3) << 1) + e;
                float v0 = c[t][nt][e], v1 = c[t][nt][2 + e];
                s0 += v0; s1 += v1;
                float bb = __ldg(&bias[n0g + n]);
                float o0 = fmaxf(v0 + bb, 0.f), o1 = fmaxf(v1 + bb, 0.f);
                if constexpr (LAYER == 1) { g_a1p[db0 + n * ocs] = pack_hl(o0); g_a1p[db1 + n * ocs] = pack_hl(o1); }
                if constexpr (LAYER == 2) { g_a2p[db0 + n * ocs] = pack_hl(o0); g_a2p[db1 + n * ocs] = pack_hl(o1); }
                if constexpr (LAYER == 3) {
                    __nv_bfloat16 h0 = __float2bfloat16_rn(o0);
                    __nv_bfloat16 h1 = __float2bfloat16_rn(o1);
                    g_a3h[db0 + n * ocs] = h0;
                    g_a3l[db0 + n * ocs] = __float2bfloat16_rn(o0 - __bfloat162float(h0));
                    g_a3h[db1 + n * ocs] = h1;
                    g_a3l[db1 + n * ocs] = __float2bfloat16_rn(o1 - __bfloat162float(h1));
                }
                if constexpr (LAYER == 4) { g_h[db0 + n0g + n] = o0; g_h[db1 + n0g + n] = o1; }
            }
        if constexpr (AVE) {
            atomicAdd(&sred[r0], s0);
            atomicAdd(&sred[r1], s1);
        }
    }
    if constexpr (AVE) {
        __syncthreads();
        for (int i = tid; i < MROWS; i += 256)
            atomicAdd(&ave[spos[i]], sred[i] * invC);
    }
}

// ---------------- fc2: [4096,512] x [2,512]^T + b ---------------------------
__global__ __launch_bounds__(256) void fc2_kernel(
    const float* __restrict__ w5, const float* __restrict__ b5,
    float* __restrict__ out) {
    int b = blockIdx.x * blockDim.x + threadIdx.x;
    if (b >= 4096) return;
    const float4* h4 = (const float4*)(g_h + (size_t)b * 512);
    const float4* wa = (const float4*)w5;
    const float4* wb = (const float4*)(w5 + 512);
    float s0 = 0.0f, s1 = 0.0f;
#pragma unroll 4
    for (int i = 0; i < 128; i++) {
        float4 h = h4[i];
        float4 a = __ldg(&wa[i]);
        float4 c = __ldg(&wb[i]);
        s0 += h.x * a.x + h.y * a.y + h.z * a.z + h.w * a.w;
        s1 += h.x * c.x + h.y * c.y + h.z * c.z + h.w * c.w;
    }
    out[b * 2 + 0] = s0 + __ldg(&b5[0]);
    out[b * 2 + 1] = s1 + __ldg(&b5[1]);
}

// ---------------- launch ----------------------------------------------------
extern "C" void kernel_launch(void* const* d_in, const int* in_sizes, int n_in,
                              void* d_out, int out_size) {
    const float* x  = (const float*)d_in[0];
    const float* w1 = (const float*)d_in[1];
    const float* b1 = (const float*)d_in[2];
    const float* w2 = (const float*)d_in[3];
    const float* b2 = (const float*)d_in[4];
    const float* w3 = (const float*)d_in[5];
    const float* b3 = (const float*)d_in[6];
    const float* w4 = (const float*)d_in[7];
    const float* b4 = (const float*)d_in[8];
    const float* w5 = (const float*)d_in[9];
    const float* b5 = (const float*)d_in[10];

    float* out  = (float*)d_out;
    float* ave1 = out + 8192;        // 165
    float* ave2 = out + 8192 + 165;  // 35
    float* ave3 = out + 8192 + 200;  // 15

    prep_w_kernel<<<1920, 256>>>(w1, w2, w3, w4);
    aveinit_kernel<<<1, 256>>>(b1, b2, b3, out);

    // dynamic smem: 2*BUF + 4*K + 16*MROWS ; BUF = 160*MROWS + 160*NT
    const int sm1 = 2 * (160 * 256 + 160 * 32) + 4 * 192 + 16 * 256;  // 97024
    const int sm2 = 2 * (160 * 128 + 160 * 64) + 4 * 288 + 16 * 128;  // 64640
    const int sm3 = 2 * (160 * 128 + 160 * 64) + 4 * 576 + 16 * 128;  // 65792
    const int sm4 = 2 * (160 * 128 + 160 * 64) + 4 * 960 + 16 * 128;  // 67328
    cudaFuncSetAttribute(conv_hmma<1, 32, 32, 256>, cudaFuncAttributeMaxDynamicSharedMemorySize, sm1);
    cudaFuncSetAttribute(conv_hmma<2, 64, 32, 128>, cudaFuncAttributeMaxDynamicSharedMemorySize, sm2);
    cudaFuncSetAttribute(conv_hmma<3, 64, 32, 128>, cudaFuncAttributeMaxDynamicSharedMemorySize, sm3);
    cudaFuncSetAttribute(conv_hmma<4, 64, 32, 128>, cudaFuncAttributeMaxDynamicSharedMemorySize, sm4);

    conv_hmma<1, 32, 32, 256><<<2640, 256, sm1>>>(x, b1, ave1);          // M=675840
    conv_hmma<2, 64, 32, 128><<<1120, 256, sm2>>>(nullptr, b2, ave2);    // M=143360
    conv_hmma<3, 64, 32, 128><<<480, 256, sm3>>>(nullptr, b3, ave3);     // M=61440
    {
        dim3 grid(32, 8);                                                // M=4096, N=512
        conv_hmma<4, 64, 32, 128><<<grid, 256, sm4>>>(nullptr, b4, nullptr);
    }
    fc2_kernel<<<16, 256>>>(w5, b5, out);
}

// round 17
// speedup vs baseline: 1.8560x; 1.0535x over previous
#include <cuda_runtime.h>
#include <cuda_bf16.h>
#include <cstdint>

typedef unsigned int u32;

// ---------------- scratch (device globals; no allocations allowed) ----------
__device__ u32  g_a1p[4096u*5280u];   // packed (hi,lo) post-relu conv1 [img][oc][165]
__device__ u32  g_a2p[4096u*2240u];   // packed post-relu conv2 [img][oc][35]
__device__ u32  g_a3p[4096u*960u];    // packed post-relu conv3 [img][chw960]
__device__ float g_h [4096u*512u];    // fp32 post-relu fc1
// fragment-ordered weights: [kblk][nblk][lane] -> uint2 (b0,b1), hi/lo planes
__device__ u32 g_f1h[12*4*64],    g_f1l[12*4*64];     // conv1 K=192,N=32
__device__ u32 g_f2h[18*8*64],    g_f2l[18*8*64];     // conv2 K=288,N=64
__device__ u32 g_f3h[36*8*64],    g_f3l[36*8*64];     // conv3 K=576,N=64
__device__ u32 g_f4h[60*64*64],   g_f4l[60*64*64];    // fc1   K=960,N=512
__device__ int g_off1[192], g_off2[288], g_off3[576];

// ---------------- helpers ----------------------------------------------------
__device__ __forceinline__ u32 pack_hl(float v) {
    __nv_bfloat16 h = __float2bfloat16_rn(v);
    float r = v - __bfloat162float(h);
    __nv_bfloat16 l = __float2bfloat16_rn(r);
    return ((u32)__bfloat16_as_ushort(h) << 16) | (u32)__bfloat16_as_ushort(l);
}

#define MMA16816(c, a0, a1, a2, a3, b0, b1)                                   \
    asm volatile("mma.sync.aligned.m16n8k16.row.col.f32.bf16.bf16.f32 "       \
        "{%0,%1,%2,%3}, {%4,%5,%6,%7}, {%8,%9}, {%0,%1,%2,%3};"               \
        : "+f"((c)[0]), "+f"((c)[1]), "+f"((c)[2]), "+f"((c)[3])              \
        : "r"(a0), "r"(a1), "r"(a2), "r"(a3), "r"(b0), "r"(b1))

// ---------------- prep: fragment-ordered split weights + offset tables ------
__device__ __forceinline__ void frag_entry(const float* w, int K, int i, int NBT,
                                           u32* fh, u32* fl) {
    // i indexes u32 entries: bit0 = r (b0/b1), bits1..5 = lane, rest = nblk/kblk
    int r = i & 1, l = (i >> 1) & 31, rest = i >> 6;
    int nblk = rest % NBT, kblk = rest / NBT;
    int n = nblk * 8 + (l >> 2);
    int k = kblk * 16 + ((l & 3) << 1) + r * 8;
    float v0 = w[n * K + k], v1 = w[n * K + k + 1];
    __nv_bfloat16 h0 = __float2bfloat16_rn(v0), h1 = __float2bfloat16_rn(v1);
    __nv_bfloat16 l0 = __float2bfloat16_rn(v0 - __bfloat162float(h0));
    __nv_bfloat16 l1 = __float2bfloat16_rn(v1 - __bfloat162float(h1));
    fh[i] = (u32)__bfloat16_as_ushort(h0) | ((u32)__bfloat16_as_ushort(h1) << 16);
    fl[i] = (u32)__bfloat16_as_ushort(l0) | ((u32)__bfloat16_as_ushort(l1) << 16);
}

__global__ void prep_w_kernel(const float* __restrict__ w1,
                              const float* __restrict__ w2,
                              const float* __restrict__ w3,
                              const float* __restrict__ w4) {
    u32 i = blockIdx.x * blockDim.x + threadIdx.x;     // grid covers 245760
    if (i < 12u*4*64)  frag_entry(w1, 192, i, 4,  g_f1h, g_f1l);
    if (i < 18u*8*64)  frag_entry(w2, 288, i, 8,  g_f2h, g_f2l);
    if (i < 36u*8*64)  frag_entry(w3, 576, i, 8,  g_f3h, g_f3l);
    if (i < 60u*64*64) frag_entry(w4, 960, i, 64, g_f4h, g_f4l);
    if (i < 192) { int ci = i >> 6, r = i & 63; g_off1[i] = ci * 3072 + (r >> 3) * 64 + (r & 7); }
    if (i < 288) { int ci = i / 9, r = i % 9; g_off2[i] = ci * 165 + (r / 3) * 15 + r % 3; }
    if (i < 576) { int ci = i / 9, r = i % 9; g_off3[i] = ci * 35 + (r / 3) * 7 + r % 3; }
}

__global__ void aveinit_kernel(const float* __restrict__ b1,
                               const float* __restrict__ b2,
                               const float* __restrict__ b3,
                               float* __restrict__ out) {
    int t = threadIdx.x;
    if (t < 165) {
        float s = 0.f; for (int c = 0; c < 32; c++) s += b1[c];
        out[8192 + t] = 4096.f * s / 32.f;
    } else if (t < 200) {
        float s = 0.f; for (int c = 0; c < 64; c++) s += b2[c];
        out[8192 + 165 + (t - 165)] = 4096.f * s / 64.f;
    } else if (t < 215) {
        float s = 0.f; for (int c = 0; c < 64; c++) s += b3[c];
        out[8192 + 200 + (t - 200)] = 4096.f * s / 64.f;
    }
}

// ---------------- register-direct HMMA gather-GEMM --------------------------
// bf16-split D = AhBh + AhBl + AlBh, fp32 acc. NO smem staging: each thread
// gathers exactly its own mma fragment elements from global (A) and loads
// pre-fragment-ordered weights (B) as coalesced uint2. No mainloop barriers.
// A raw pairs double-buffered in regs (perm/pack deferred to use).
template<int LAYER, int NT, int MROWS>
__global__ __launch_bounds__(256, 2) void conv_frag(
    const float* __restrict__ src_ext,   // LAYER==1: x (fp32)
    const float* __restrict__ bias, float* __restrict__ ave) {

    constexpr int K       = LAYER == 1 ? 192  : LAYER == 2 ? 288 : LAYER == 3 ? 576 : 960;
    constexpr int Ntot    = LAYER == 1 ? 32   : LAYER == 4 ? 512 : 64;
    constexpr int NBT     = Ntot / 8;
    constexpr int npos    = LAYER == 1 ? 165  : LAYER == 2 ? 35  : LAYER == 3 ? 15  : 1;
    constexpr int imgstr  = LAYER == 1 ? 9216 : LAYER == 2 ? 5280: LAYER == 3 ? 2240: 960;
    constexpr int PW      = LAYER == 1 ? 15   : LAYER == 2 ? 7   : LAYER == 3 ? 5   : 1;
    constexpr int rowstep = LAYER == 1 ? 256  : LAYER == 2 ? 30  : LAYER == 3 ? 7   : 0;
    constexpr int colstep = LAYER == 1 ? 4    : LAYER == 2 ? 2   : LAYER == 3 ? 1   : 0;
    constexpr int ocs     = LAYER == 1 ? 165  : LAYER == 2 ? 35  : LAYER == 3 ? 15  : 1;
    constexpr int cstride = LAYER == 1 ? 5280 : LAYER == 2 ? 2240: LAYER == 3 ? 960 : 512;
    constexpr float invC  = LAYER == 1 ? (1.f / 32.f) : (1.f / 64.f);
    constexpr bool AVE    = LAYER != 4;
    constexpr int NCH = K / 32;              // 32-k chunks
    constexpr int MT  = 2;                   // m16 tiles per warp (WM=32)
    constexpr int NWN = NT / 32;             // n-warps
    constexpr int WM  = 32;

    const u32* srcp; const u32 *fbh, *fbl; const int* offtab;
    if constexpr (LAYER == 1) { srcp = nullptr; offtab = g_off1; fbh = g_f1h; fbl = g_f1l; }
    if constexpr (LAYER == 2) { srcp = g_a1p; offtab = g_off2; fbh = g_f2h; fbl = g_f2l; }
    if constexpr (LAYER == 3) { srcp = g_a2p; offtab = g_off3; fbh = g_f3h; fbl = g_f3l; }
    if constexpr (LAYER == 4) { srcp = g_a3p; offtab = nullptr; fbh = g_f4h; fbl = g_f4l; }

    extern __shared__ __align__(16) char smem[];
    int* soff  = (int*)smem;              // [K] (conv layers)
    int* sbase = soff + K;                // [MROWS]
    int* sdst  = sbase + MROWS;           // [MROWS]
    int* spos  = sdst + MROWS;            // [MROWS]
    float* sred = (float*)(spos + MROWS); // [MROWS]

    const int tid = threadIdx.x;
    const int wid = tid >> 5, l = tid & 31;
    const int wm = wid / NWN, wn = wid % NWN;
    const int m0 = blockIdx.x * MROWS;
    const int n0g = (LAYER == 4) ? blockIdx.y * 64 : 0;
    const int nb0 = n0g / 8 + wn * 4;

    if constexpr (LAYER != 4)
        for (int i = tid; i < K; i += 256) soff[i] = offtab[i];
    for (int i = tid; i < MROWS; i += 256) {
        int m = m0 + i;
        int img = m / npos, pos = m - img * npos;
        int py = pos / PW, px = pos - py * PW;
        sbase[i] = img * imgstr + py * rowstep + px * colstep;
        sdst[i]  = img * cstride + pos;
        spos[i]  = pos;
        sred[i]  = 0.f;
    }
    __syncthreads();

    // this thread's fragment rows: row = wm*32 + t*16 + rh*8 + l/4
    int rb[4];
#pragma unroll
    for (int t = 0; t < MT; t++)
#pragma unroll
        for (int rh = 0; rh < 2; rh++)
            rb[t * 2 + rh] = sbase[wm * WM + t * 16 + rh * 8 + (l >> 2)];
    const int kl = l & 3;   // k-pair lane index

    float c[MT][4][4];
#pragma unroll
    for (int t = 0; t < MT; t++)
#pragma unroll
        for (int n = 0; n < 4; n++)
#pragma unroll
            for (int e = 0; e < 4; e++) c[t][n][e] = 0.f;

    // raw A pair buffers (perm/pack deferred to use time)
    u32 Pa0[16], Pa1[16], Pb0[16], Pb1[16];

    // gather chunk cc raw pairs into (q0,q1); e = ks8*8 + qk*4 + rh*2 + t
    auto gatherA = [&](int cc, u32 (&q0)[16], u32 (&q1)[16]) {
#pragma unroll
        for (int e = 0; e < 16; e++) {
            const int ks8 = e >> 3, qk = (e >> 2) & 1, rh = (e >> 1) & 1, t = e & 1;
            const int kp = cc * 16 + ks8 * 8 + qk * 4 + kl;
            const int base = rb[t * 2 + rh];
            if constexpr (LAYER == 1) {
                float2 v = *(const float2*)(src_ext + base + soff[2 * kp]);
                q0[e] = __float_as_uint(v.x); q1[e] = __float_as_uint(v.y);
            } else if constexpr (LAYER == 4) {
                uint2 v = *(const uint2*)(srcp + base + 2 * kp);
                q0[e] = v.x; q1[e] = v.y;
            } else {
                q0[e] = srcp[base + soff[2 * kp]];
                q1[e] = srcp[base + soff[2 * kp + 1]];
            }
        }
    };

    // mma one chunk from raw buffers
    auto mmaChunk = [&](int cc, u32 (&q0)[16], u32 (&q1)[16]) {
#pragma unroll
        for (int ks8 = 0; ks8 < 2; ks8++) {
            const int kblk = cc * 2 + ks8;
            uint2 bh2[4], bl2[4];
#pragma unroll
            for (int nt = 0; nt < 4; nt++) {
                int idx = (kblk * NBT + nb0 + nt) * 32 + l;
                bh2[nt] = ((const uint2*)fbh)[idx];
                bl2[nt] = ((const uint2*)fbl)[idx];
            }
#pragma unroll
            for (int t = 0; t < MT; t++) {
                u32 ah[4], al[4];
#pragma unroll
                for (int f = 0; f < 4; f++) {   // f: a0..a3 -> (qk = f>>1, rh = f&1)
                    const int e = ks8 * 8 + (f >> 1) * 4 + (f & 1) * 2 + t;
                    u32 p0, p1;
                    if constexpr (LAYER == 1) {
                        p0 = pack_hl(__uint_as_float(q0[e]));
                        p1 = pack_hl(__uint_as_float(q1[e]));
                    } else { p0 = q0[e]; p1 = q1[e]; }
                    ah[f] = __byte_perm(p0, p1, 0x7632);
                    al[f] = __byte_perm(p0, p1, 0x5410);
                }
#pragma unroll
                for (int nt = 0; nt < 4; nt++) {
                    MMA16816(c[t][nt], ah[0], ah[1], ah[2], ah[3], bh2[nt].x, bh2[nt].y);
                    MMA16816(c[t][nt], ah[0], ah[1], ah[2], ah[3], bl2[nt].x, bl2[nt].y);
                    MMA16816(c[t][nt], al[0], al[1], al[2], al[3], bh2[nt].x, bh2[nt].y);
                }
            }
        }
    };

    gatherA(0, Pa0, Pa1);
#pragma unroll 1
    for (int cc = 0; cc < NCH; cc += 2) {
        if (cc + 1 < NCH) gatherA(cc + 1, Pb0, Pb1);
        mmaChunk(cc, Pa0, Pa1);
        if (cc + 1 < NCH) {
            if (cc + 2 < NCH) gatherA(cc + 2, Pa0, Pa1);
            mmaChunk(cc + 1, Pb0, Pb1);
        }
    }

    // ---- epilogue: bias + relu (+ pack), ave row sums ----
#pragma unroll
    for (int t = 0; t < MT; t++) {
        int r0 = wm * WM + t * 16 + (l >> 2);
        int r1 = r0 + 8;
        int db0 = sdst[r0], db1 = sdst[r1];
        float s0 = 0.f, s1 = 0.f;
#pragma unroll
        for (int nt = 0; nt < 4; nt++)
#pragma unroll
            for (int e = 0; e < 2; e++) {
                int n = wn * 32 + nt * 8 + ((l & 3) << 1) + e;
                float v0 = c[t][nt][e], v1 = c[t][nt][2 + e];
                s0 += v0; s1 += v1;
                float bb = __ldg(&bias[n0g + n]);
                float o0 = fmaxf(v0 + bb, 0.f), o1 = fmaxf(v1 + bb, 0.f);
                if constexpr (LAYER == 1) { g_a1p[db0 + n * ocs] = pack_hl(o0); g_a1p[db1 + n * ocs] = pack_hl(o1); }
                if constexpr (LAYER == 2) { g_a2p[db0 + n * ocs] = pack_hl(o0); g_a2p[db1 + n * ocs] = pack_hl(o1); }
                if constexpr (LAYER == 3) { g_a3p[db0 + n * ocs] = pack_hl(o0); g_a3p[db1 + n * ocs] = pack_hl(o1); }
                if constexpr (LAYER == 4) { g_h[db0 + n0g + n] = o0; g_h[db1 + n0g + n] = o1; }
            }
        if constexpr (AVE) {
            atomicAdd(&sred[r0], s0);
            atomicAdd(&sred[r1], s1);
        }
    }
    if constexpr (AVE) {
        __syncthreads();
        for (int i = tid; i < MROWS; i += 256)
            atomicAdd(&ave[spos[i]], sred[i] * invC);
    }
}

// ---------------- fc2: [4096,512] x [2,512]^T + b ---------------------------
__global__ __launch_bounds__(256) void fc2_kernel(
    const float* __restrict__ w5, const float* __restrict__ b5,
    float* __restrict__ out) {
    int b = blockIdx.x * blockDim.x + threadIdx.x;
    if (b >= 4096) return;
    const float4* h4 = (const float4*)(g_h + (size_t)b * 512);
    const float4* wa = (const float4*)w5;
    const float4* wb = (const float4*)(w5 + 512);
    float s0 = 0.0f, s1 = 0.0f;
#pragma unroll 4
    for (int i = 0; i < 128; i++) {
        float4 h = h4[i];
        float4 a = __ldg(&wa[i]);
        float4 c = __ldg(&wb[i]);
        s0 += h.x * a.x + h.y * a.y + h.z * a.z + h.w * a.w;
        s1 += h.x * c.x + h.y * c.y + h.z * c.z + h.w * c.w;
    }
    out[b * 2 + 0] = s0 + __ldg(&b5[0]);
    out[b * 2 + 1] = s1 + __ldg(&b5[1]);
}

// ---------------- launch ----------------------------------------------------
extern "C" void kernel_launch(void* const* d_in, const int* in_sizes, int n_in,
                              void* d_out, int out_size) {
    const float* x  = (const float*)d_in[0];
    const float* w1 = (const float*)d_in[1];
    const float* b1 = (const float*)d_in[2];
    const float* w2 = (const float*)d_in[3];
    const float* b2 = (const float*)d_in[4];
    const float* w3 = (const float*)d_in[5];
    const float* b3 = (const float*)d_in[6];
    const float* w4 = (const float*)d_in[7];
    const float* b4 = (const float*)d_in[8];
    const float* w5 = (const float*)d_in[9];
    const float* b5 = (const float*)d_in[10];

    float* out  = (float*)d_out;
    float* ave1 = out + 8192;        // 165
    float* ave2 = out + 8192 + 165;  // 35
    float* ave3 = out + 8192 + 200;  // 15

    prep_w_kernel<<<960, 256>>>(w1, w2, w3, w4);   // 245760 threads
    aveinit_kernel<<<1, 256>>>(b1, b2, b3, out);

    // smem: 4*K + 16*MROWS (tables only; all < 8KB)
    const int sm1 = 4 * 192 + 16 * 256;   // 4864
    const int sm2 = 4 * 288 + 16 * 128;   // 3200
    const int sm3 = 4 * 576 + 16 * 128;   // 4352
    const int sm4 = 4 * 960 + 16 * 128;   // 5888

    conv_frag<1, 32, 256><<<2640, 256, sm1>>>(x, b1, ave1);        // M=675840
    conv_frag<2, 64, 128><<<1120, 256, sm2>>>(nullptr, b2, ave2);  // M=143360
    conv_frag<3, 64, 128><<<480, 256, sm3>>>(nullptr, b3, ave3);   // M=61440
    {
        dim3 grid(32, 8);                                          // M=4096, N=512
        conv_frag<4, 64, 128><<<grid, 256, sm4>>>(nullptr, b4, nullptr);
    }
    fc2_kernel<<<16, 256>>>(w5, b5, out);
}